// round 1
// baseline (speedup 1.0000x reference)
#include <cuda_runtime.h>

// Problem constants (fixed shapes per reference)
#define B_       2
#define S_       2048
#define DM_      1024
#define NH_      16
#define DK_      64
#define ROWS_    (B_ * S_)          // 4096
#define QKCOLS_  2048               // q (0..1023) | k (1024..2047); V is dead code

// Scratch (static __device__ — no allocation in kernel_launch)
__device__ float g_qk [(size_t)ROWS_ * QKCOLS_];        // [4096][2048]
__device__ float g_T  [(size_t)B_ * DM_ * DM_];         // [2][1024][1024]
__device__ float g_mid[(size_t)ROWS_ * DM_];            // out before LN

// ---------------------------------------------------------------------------
// Generic tiled SGEMM:  C = alpha * (A @ B) + bias   (row-major, no bounds
// checks: all dims used are multiples of the tile sizes).
// BM=BN=128, BK=16, TM=TN=8, 256 threads. blockIdx.z = batch via strides.
// ---------------------------------------------------------------------------
__global__ __launch_bounds__(256)
void sgemm_bias(const float* __restrict__ A, int lda, long sA,
                const float* __restrict__ B, int ldb, long sB,
                float* __restrict__ C, int ldc, long sC,
                const float* __restrict__ bias, int K, float alpha)
{
    __shared__ float As[16][128];   // [k][m] (transposed)
    __shared__ float Bs[16][128];   // [k][n]

    A += (long)blockIdx.z * sA + (long)blockIdx.y * 128 * lda;
    B += (long)blockIdx.z * sB + blockIdx.x * 128;
    C += (long)blockIdx.z * sC + (long)blockIdx.y * 128 * ldc + blockIdx.x * 128;
    bias += blockIdx.x * 128;

    const int tid  = threadIdx.x;
    const int tr   = tid >> 4;          // 0..15
    const int tc   = tid & 15;          // 0..15
    const int arow = tid >> 2;          // 0..63 (and +64)
    const int acol = (tid & 3) << 2;    // 0,4,8,12
    const int brow = tid >> 5;          // 0..7 (and +8)
    const int bcol = (tid & 31) << 2;   // 0..124

    float acc[8][8] = {};

    for (int k0 = 0; k0 < K; k0 += 16) {
        #pragma unroll
        for (int r = 0; r < 2; r++) {
            const int row = arow + r * 64;
            const float4 v = *(const float4*)(A + (long)row * lda + k0 + acol);
            As[acol + 0][row] = v.x;
            As[acol + 1][row] = v.y;
            As[acol + 2][row] = v.z;
            As[acol + 3][row] = v.w;
        }
        #pragma unroll
        for (int r = 0; r < 2; r++) {
            const int row = brow + r * 8;
            *(float4*)&Bs[row][bcol] =
                *(const float4*)(B + (long)(k0 + row) * ldb + bcol);
        }
        __syncthreads();

        #pragma unroll
        for (int kk = 0; kk < 16; kk++) {
            float a[8], b[8];
            *(float4*)(a)     = *(const float4*)&As[kk][tr * 8];
            *(float4*)(a + 4) = *(const float4*)&As[kk][tr * 8 + 4];
            *(float4*)(b)     = *(const float4*)&Bs[kk][tc * 8];
            *(float4*)(b + 4) = *(const float4*)&Bs[kk][tc * 8 + 4];
            #pragma unroll
            for (int i = 0; i < 8; i++)
                #pragma unroll
                for (int j = 0; j < 8; j++)
                    acc[i][j] = fmaf(a[i], b[j], acc[i][j]);
        }
        __syncthreads();
    }

    float bb[8];
    *(float4*)(bb)     = *(const float4*)(bias + tc * 8);
    *(float4*)(bb + 4) = *(const float4*)(bias + tc * 8 + 4);

    #pragma unroll
    for (int i = 0; i < 8; i++) {
        float* dst = C + (long)(tr * 8 + i) * ldc + tc * 8;
        float4 v0, v1;
        v0.x = fmaf(alpha, acc[i][0], bb[0]);
        v0.y = fmaf(alpha, acc[i][1], bb[1]);
        v0.z = fmaf(alpha, acc[i][2], bb[2]);
        v0.w = fmaf(alpha, acc[i][3], bb[3]);
        v1.x = fmaf(alpha, acc[i][4], bb[4]);
        v1.y = fmaf(alpha, acc[i][5], bb[5]);
        v1.z = fmaf(alpha, acc[i][6], bb[6]);
        v1.w = fmaf(alpha, acc[i][7], bb[7]);
        *(float4*)(dst)     = v0;
        *(float4*)(dst + 4) = v1;
    }
}

// ---------------------------------------------------------------------------
// T[b, n*64+k, d] = (1/8) * sum_j K[b,j,n,k] * w_fc[j*16+n, d]
// One block: all 128 "m" rows (b0:k0..63 | b1:k0..63) x 128 d-cols for head n,
// contracting over j=0..2047. grid = (8 d-tiles, 16 heads). w_fc read ONCE.
// ---------------------------------------------------------------------------
__global__ __launch_bounds__(256)
void gemm_T_kernel(const float* __restrict__ qk,   // [4096][2048]
                   const float* __restrict__ wfc,  // [32768][1024]
                   float* __restrict__ T)          // [2][1024][1024]
{
    __shared__ float As[16][128];   // [j_local][m]   m = b*64 + k
    __shared__ float Bs[16][128];   // [j_local][d]

    const int n     = blockIdx.y;
    const int dcol0 = blockIdx.x * 128;
    const int tid   = threadIdx.x;
    const int tr    = tid >> 4;
    const int tc    = tid & 15;

    const int aj  = tid >> 4;          // j_local 0..15
    const int am4 = (tid & 15) << 2;   // k 0,4,..,60

    float acc[8][8] = {};

    for (int j0 = 0; j0 < S_; j0 += 16) {
        #pragma unroll
        for (int r = 0; r < 2; r++) {   // r = batch
            const float4 v = *(const float4*)(qk
                + (size_t)(r * S_ + j0 + aj) * QKCOLS_
                + DM_ + n * DK_ + am4);
            *(float4*)&As[aj][r * 64 + am4] = v;
        }
        #pragma unroll
        for (int r = 0; r < 2; r++) {
            const int e  = tid + r * 256;
            const int bj = e >> 5;
            const int c4 = (e & 31) << 2;
            *(float4*)&Bs[bj][c4] = *(const float4*)(wfc
                + (size_t)((j0 + bj) * NH_ + n) * DM_ + dcol0 + c4);
        }
        __syncthreads();

        #pragma unroll
        for (int kk = 0; kk < 16; kk++) {
            float a[8], b[8];
            *(float4*)(a)     = *(const float4*)&As[kk][tr * 8];
            *(float4*)(a + 4) = *(const float4*)&As[kk][tr * 8 + 4];
            *(float4*)(b)     = *(const float4*)&Bs[kk][tc * 8];
            *(float4*)(b + 4) = *(const float4*)&Bs[kk][tc * 8 + 4];
            #pragma unroll
            for (int i = 0; i < 8; i++)
                #pragma unroll
                for (int j = 0; j < 8; j++)
                    acc[i][j] = fmaf(a[i], b[j], acc[i][j]);
        }
        __syncthreads();
    }

    const float inv_sqrt_dk = 0.125f;   // 1/sqrt(64)
    #pragma unroll
    for (int i = 0; i < 8; i++) {
        const int m = tr * 8 + i;       // 0..127; batch = m/64, k = m%64
        float* dst = T + (size_t)(m >> 6) * DM_ * DM_
                       + (size_t)(n * DK_ + (m & 63)) * DM_ + dcol0 + tc * 8;
        float4 v0, v1;
        v0.x = acc[i][0] * inv_sqrt_dk;
        v0.y = acc[i][1] * inv_sqrt_dk;
        v0.z = acc[i][2] * inv_sqrt_dk;
        v0.w = acc[i][3] * inv_sqrt_dk;
        v1.x = acc[i][4] * inv_sqrt_dk;
        v1.y = acc[i][5] * inv_sqrt_dk;
        v1.z = acc[i][6] * inv_sqrt_dk;
        v1.w = acc[i][7] * inv_sqrt_dk;
        *(float4*)(dst)     = v0;
        *(float4*)(dst + 4) = v1;
    }
}

// ---------------------------------------------------------------------------
// Residual + LayerNorm: one block per row (4096 rows, 256 threads, 4 elem/thr)
// ---------------------------------------------------------------------------
__device__ __forceinline__ float warp_sum(float v) {
    #pragma unroll
    for (int o = 16; o > 0; o >>= 1) v += __shfl_down_sync(0xFFFFFFFFu, v, o);
    return v;
}

__global__ __launch_bounds__(256)
void ln_kernel(const float* __restrict__ x, const float* __restrict__ mid,
               const float* __restrict__ gamma, const float* __restrict__ beta,
               float* __restrict__ y)
{
    __shared__ float red[2][8];
    const long row = blockIdx.x;
    const int  c   = threadIdx.x * 4;
    const int  wid = threadIdx.x >> 5;
    const int  lan = threadIdx.x & 31;

    const float4 xv = *(const float4*)(x   + row * DM_ + c);
    const float4 ov = *(const float4*)(mid + row * DM_ + c);
    float v0 = xv.x + ov.x, v1 = xv.y + ov.y, v2 = xv.z + ov.z, v3 = xv.w + ov.w;

    float s  = v0 + v1 + v2 + v3;
    float ss = v0 * v0 + v1 * v1 + v2 * v2 + v3 * v3;
    s  = warp_sum(s);
    ss = warp_sum(ss);
    if (lan == 0) { red[0][wid] = s; red[1][wid] = ss; }
    __syncthreads();
    if (wid == 0) {
        float a = (lan < 8) ? red[0][lan] : 0.0f;
        float b = (lan < 8) ? red[1][lan] : 0.0f;
        a = warp_sum(a);
        b = warp_sum(b);
        if (lan == 0) { red[0][0] = a * (1.0f / DM_); red[1][0] = b * (1.0f / DM_); }
    }
    __syncthreads();

    const float mean = red[0][0];
    const float var  = red[1][0] - mean * mean;
    const float rstd = rsqrtf(var + 1e-5f);

    const float4 gv = *(const float4*)(gamma + c);
    const float4 bv = *(const float4*)(beta  + c);
    float4 out;
    out.x = gv.x * (v0 - mean) * rstd + bv.x;
    out.y = gv.y * (v1 - mean) * rstd + bv.y;
    out.z = gv.z * (v2 - mean) * rstd + bv.z;
    out.w = gv.w * (v3 - mean) * rstd + bv.w;
    *(float4*)(y + row * DM_ + c) = out;
}

// ---------------------------------------------------------------------------
extern "C" void kernel_launch(void* const* d_in, const int* in_sizes, int n_in,
                              void* d_out, int out_size)
{
    const float* x     = (const float*)d_in[0];
    const float* w_qkv = (const float*)d_in[1];
    const float* b_qkv = (const float*)d_in[2];
    const float* w_fc  = (const float*)d_in[3];
    const float* b_fc  = (const float*)d_in[4];
    const float* gamma = (const float*)d_in[5];
    const float* beta  = (const float*)d_in[6];
    float* out = (float*)d_out;

    float *qk, *T, *mid;
    cudaGetSymbolAddress((void**)&qk,  g_qk);
    cudaGetSymbolAddress((void**)&T,   g_T);
    cudaGetSymbolAddress((void**)&mid, g_mid);

    // 1) Q|K projection: [4096,1024] @ w_qkv[:, 0:2048] + b_qkv[0:2048]
    //    (V is dead code in the reference and never computed.)
    sgemm_bias<<<dim3(QKCOLS_ / 128, ROWS_ / 128, 1), 256>>>(
        x, DM_, 0L,
        w_qkv, 3 * DM_, 0L,
        qk, QKCOLS_, 0L,
        b_qkv, DM_, 1.0f);

    // 2) T[b, n*64+k, d] = (1/8) * K_{b,n}^T @ W_n   (reads w_fc exactly once)
    gemm_T_kernel<<<dim3(DM_ / 128, NH_), 256>>>(qk, w_fc, T);

    // 3) out[b] = Q[b] @ T[b] + b_fc   (batched over z)
    sgemm_bias<<<dim3(DM_ / 128, S_ / 128, B_), 256>>>(
        qk, QKCOLS_, (long)S_ * QKCOLS_,
        T, DM_, (long)DM_ * DM_,
        mid, DM_, (long)S_ * DM_,
        b_fc, DM_, 1.0f);

    // 4) y = LN(x + out) * gamma + beta
    ln_kernel<<<ROWS_, 256>>>(x, mid, gamma, beta, out);
}

// round 4
// speedup vs baseline: 2.2991x; 2.2991x over previous
#include <cuda_runtime.h>
#include <cuda_bf16.h>
#include <cstdint>

// ---------------------------------------------------------------------------
// Problem constants
// ---------------------------------------------------------------------------
#define B_       2
#define S_       2048
#define DM_      1024
#define NH_      16
#define ROWS_    (B_ * S_)          // 4096

// ---------------------------------------------------------------------------
// Scratch (__device__ globals; no allocation at launch). 1024B-aligned.
// bf16 "split" buffers store [hi | lo] along the contraction dim (2K wide).
// ---------------------------------------------------------------------------
__device__ __align__(1024) __nv_bfloat16 g_A1 [(size_t)ROWS_ * 2048];     // x split
__device__ __align__(1024) __nv_bfloat16 g_B1t[(size_t)2048 * 2048];      // w_qkv[:,:2048]^T split
__device__ __align__(1024) float         g_qk [(size_t)ROWS_ * 2048];     // q|k fp32
__device__ __align__(1024) __nv_bfloat16 g_A3 [(size_t)ROWS_ * 2048];     // Q split
__device__ __align__(1024) __nv_bfloat16 g_A2 [(size_t)NH_ * 128 * 4096]; // K^T split
__device__ __align__(1024) __nv_bfloat16 g_B2t[(size_t)NH_ * DM_ * 4096]; // w_fc^T split
__device__ __align__(1024) float         g_Tt [(size_t)NH_ * 128 * DM_];  // T tmp fp32
__device__ __align__(1024) __nv_bfloat16 g_B3t[(size_t)B_ * DM_ * 2048];  // T^T split
__device__ __align__(1024) float         g_mid[(size_t)ROWS_ * DM_];      // pre-LN out
__device__ __align__(1024) float         g_zb [2048];                     // zero bias

// ---------------------------------------------------------------------------
// PTX helpers (baseline sm_100 ISA only: cp.async, ldmatrix, mma.sync)
// ---------------------------------------------------------------------------
__device__ __forceinline__ uint32_t smem_u32(const void* p) {
    uint32_t a;
    asm("{ .reg .u64 t; cvta.to.shared.u64 t, %1; cvt.u32.u64 %0, t; }" : "=r"(a) : "l"(p));
    return a;
}

#define SW128(off) ((off) ^ (((off) >> 3) & 0x70))

#define CP_ASYNC16(dst, src) \
    asm volatile("cp.async.cg.shared.global [%0], [%1], 16;" :: "r"(dst), "l"(src))
#define CP_COMMIT() asm volatile("cp.async.commit_group;" ::: "memory")

__device__ __forceinline__ void ldsm4(uint32_t& r0, uint32_t& r1, uint32_t& r2,
                                      uint32_t& r3, uint32_t addr) {
    asm volatile("ldmatrix.sync.aligned.m8n8.x4.shared.b16 {%0,%1,%2,%3}, [%4];"
                 : "=r"(r0), "=r"(r1), "=r"(r2), "=r"(r3) : "r"(addr));
}

__device__ __forceinline__ void mma16816(float* d, const uint32_t* a, const uint32_t* b) {
    asm volatile("mma.sync.aligned.m16n8k16.row.col.f32.bf16.bf16.f32 "
                 "{%0,%1,%2,%3}, {%4,%5,%6,%7}, {%8,%9}, {%0,%1,%2,%3};"
                 : "+f"(d[0]), "+f"(d[1]), "+f"(d[2]), "+f"(d[3])
                 : "r"(a[0]), "r"(a[1]), "r"(a[2]), "r"(a[3]), "r"(b[0]), "r"(b[1]));
}

// ---------------------------------------------------------------------------
// Tensor-core GEMM (mma.sync):  C[M,N] = alpha * A[M,K'] @ Bt[N,K']^T + bias
// Split layout: physical row = 2K bf16 ([hi|lo]); logical K' = 3K via region
// mapping (hi*hi, lo*hi, hi*lo). Tile 128x128xBK64, 8 warps (2x4), 3 stages.
// ---------------------------------------------------------------------------
#define BK_     64
#define STAGES_ 3
#define TILE_AB (128 * BK_ * 2)            // 16 KB each for A and B
#define STAGE_  (2 * TILE_AB)              // 32 KB
#define GSMEM_  (STAGES_ * STAGE_ + 1024)  // + alignment slack

__global__ __launch_bounds__(256, 2)
void mm_gemm(const __nv_bfloat16* __restrict__ A, long lda, long sA,
             const __nv_bfloat16* __restrict__ Bt, long ldb, long sB,
             float* __restrict__ C, long ldc, long sC,
             const float* __restrict__ bias, int K, float alpha)
{
    extern __shared__ char smem[];
    const uint32_t tbase = (smem_u32(smem) + 1023) & ~1023u;
    const int tid = threadIdx.x, wid = tid >> 5, lane = tid & 31;
    const int wm = wid >> 2, wn = wid & 3;       // warp grid 2 (m) x 4 (n)

    A    += (long)blockIdx.z * sA + (long)blockIdx.y * 128 * lda;
    Bt   += (long)blockIdx.z * sB + (long)blockIdx.x * 128 * ldb;
    C    += (long)blockIdx.z * sC + (long)blockIdx.y * 128 * ldc + (long)blockIdx.x * 128;
    bias += blockIdx.x * 128;

    const int KC = K / BK_;          // chunks per region
    const int NC = 3 * KC;           // total logical chunks

    // cp.async mapping: 1024 16B-chunks per tile, 4 per thread
    const int ldrow = tid >> 3, ldc16 = (tid & 7) * 16;

    auto load_stage = [&](int chunk, int s) {
        const int region = (chunk >= 2 * KC) ? 2 : (chunk >= KC ? 1 : 0);
        const int within = chunk - region * KC;
        const long acol  = (long)(region == 1 ? K : 0) + (long)within * BK_;
        const long bcol  = (long)(region == 2 ? K : 0) + (long)within * BK_;
        const uint32_t ab = tbase + s * STAGE_;
        const uint32_t bb = ab + TILE_AB;
        #pragma unroll
        for (int r = 0; r < 4; r++) {
            const int row = ldrow + r * 32;
            CP_ASYNC16(ab + SW128(row * 128 + ldc16), A + (long)row * lda + acol + ldc16 / 2);
            CP_ASYNC16(bb + SW128(row * 128 + ldc16), Bt + (long)row * ldb + bcol + ldc16 / 2);
        }
    };

    // ldmatrix per-lane address pieces (j = lane>>3, r = lane&7)
    const int lj = lane >> 3, lr = lane & 7;
    // A x4 tile order: (m0-7,k0-7),(m8-15,k0-7),(m0-7,k8-15),(m8-15,k8-15)
    const int arow_base = wm * 64 + (lj & 1) * 8 + lr;    // + mt*16
    const int acol_base = (lj >> 1) * 16;                 // + ks*32
    // B x4 (n-tile pair p): (n0-7,k0-7),(n0-7,k8-15),(n8-15,k0-7),(n8-15,k8-15)
    const int brow_base = wn * 32 + (lj >> 1) * 8 + lr;   // + p*16
    const int bcol_base = (lj & 1) * 16;                  // + ks*32

    float acc[4][4][4] = {};   // [mt][nt][reg]

    // Prologue
    for (int c = 0; c < STAGES_ - 1; c++) { load_stage(c, c); CP_COMMIT(); }

    for (int i = 0; i < NC; i++) {
        const int pf = i + STAGES_ - 1;
        if (pf < NC) load_stage(pf, pf % STAGES_);
        CP_COMMIT();
        asm volatile("cp.async.wait_group %0;" :: "n"(STAGES_ - 1));
        __syncthreads();

        const uint32_t ab = tbase + (i % STAGES_) * STAGE_;
        const uint32_t bb = ab + TILE_AB;

        #pragma unroll
        for (int ks = 0; ks < BK_ / 16; ks++) {
            uint32_t afr[4][4], bfr[2][4];
            #pragma unroll
            for (int mt = 0; mt < 4; mt++) {
                const int row = arow_base + mt * 16;
                const int col = acol_base + ks * 32;
                ldsm4(afr[mt][0], afr[mt][1], afr[mt][2], afr[mt][3],
                      ab + row * 128 + (col ^ ((row & 7) << 4)));
            }
            #pragma unroll
            for (int p = 0; p < 2; p++) {
                const int row = brow_base + p * 16;
                const int col = bcol_base + ks * 32;
                ldsm4(bfr[p][0], bfr[p][1], bfr[p][2], bfr[p][3],
                      bb + row * 128 + (col ^ ((row & 7) << 4)));
            }
            #pragma unroll
            for (int mt = 0; mt < 4; mt++)
                #pragma unroll
                for (int nt = 0; nt < 4; nt++)
                    mma16816(acc[mt][nt], afr[mt], &bfr[nt >> 1][(nt & 1) * 2]);
        }
        __syncthreads();
    }

    // Epilogue: direct global stores (fp32), bias + alpha
    const int erow = wm * 64 + (lane >> 2);
    const int ecol = wn * 32 + (lane & 3) * 2;
    #pragma unroll
    for (int mt = 0; mt < 4; mt++) {
        #pragma unroll
        for (int nt = 0; nt < 4; nt++) {
            const int col = ecol + nt * 8;
            const float b0 = bias[col], b1 = bias[col + 1];
            float2 v;
            v.x = alpha * acc[mt][nt][0] + b0;
            v.y = alpha * acc[mt][nt][1] + b1;
            *(float2*)(C + (long)(erow + mt * 16) * ldc + col) = v;
            v.x = alpha * acc[mt][nt][2] + b0;
            v.y = alpha * acc[mt][nt][3] + b1;
            *(float2*)(C + (long)(erow + mt * 16 + 8) * ldc + col) = v;
        }
    }
}

// ---------------------------------------------------------------------------
// Split conversions
// ---------------------------------------------------------------------------
__device__ __forceinline__ void split2(float a, __nv_bfloat16& h, __nv_bfloat16& l) {
    h = __float2bfloat16(a);
    l = __float2bfloat16(a - __bfloat162float(h));
}

// Row-major split: out[r][c]=hi(in[r][c]), out[r][Csel+c]=lo ; out row = 2*Csel
__global__ __launch_bounds__(256)
void conv_rows(const float* __restrict__ in, long ldin,
               __nv_bfloat16* __restrict__ out, int Csel)
{
    const long idx = (long)blockIdx.x * 256 + threadIdx.x;
    const long r = idx / (Csel / 4);
    const int  c = (int)(idx % (Csel / 4)) * 4;
    const float4 v = *(const float4*)(in + r * ldin + c);
    __nv_bfloat16 h0, h1, h2, h3, l0, l1, l2, l3;
    split2(v.x, h0, l0); split2(v.y, h1, l1);
    split2(v.z, h2, l2); split2(v.w, h3, l3);
    __nv_bfloat16* po = out + r * 2 * Csel + c;
    *(__nv_bfloat162*)(po)            = __halves2bfloat162(h0, h1);
    *(__nv_bfloat162*)(po + 2)        = __halves2bfloat162(h2, h3);
    *(__nv_bfloat162*)(po + Csel)     = __halves2bfloat162(l0, l1);
    *(__nv_bfloat162*)(po + Csel + 2) = __halves2bfloat162(l2, l3);
}

// w_qkv[:, :2048] -> B1t[n][c]=hi(w[c][n]), [n][1024+c]=lo   (ld w = 3072)
__global__ void conv_wqkv(const float* __restrict__ w, __nv_bfloat16* __restrict__ out)
{
    __shared__ float t[32][33];
    const int c0 = blockIdx.y * 32, n0 = blockIdx.x * 32;
    const int tx = threadIdx.x, ty = threadIdx.y;
    #pragma unroll
    for (int r = 0; r < 4; r++)
        t[ty + 8 * r][tx] = w[(long)(c0 + ty + 8 * r) * 3072 + n0 + tx];
    __syncthreads();
    #pragma unroll
    for (int r = 0; r < 4; r++) {
        __nv_bfloat16 h, l; split2(t[tx][ty + 8 * r], h, l);
        const long base = (long)(n0 + ty + 8 * r) * 2048 + c0 + tx;
        out[base] = h; out[base + 1024] = l;
    }
}

// qk K-half -> A2[n][b*64+k][j]=hi, [..][2048+j]=lo   grid(2,128,16)
__global__ void conv_a2(const float* __restrict__ qk, __nv_bfloat16* __restrict__ out)
{
    __shared__ float t[32][33];
    const int n = blockIdx.z, jg0 = blockIdx.y * 32, k0 = blockIdx.x * 32;
    const int tx = threadIdx.x, ty = threadIdx.y;
    #pragma unroll
    for (int r = 0; r < 4; r++)
        t[ty + 8 * r][tx] = qk[(long)(jg0 + ty + 8 * r) * 2048 + 1024 + n * 64 + k0 + tx];
    __syncthreads();
    #pragma unroll
    for (int r = 0; r < 4; r++) {
        const int k = k0 + ty + 8 * r;
        const int jg = jg0 + tx, b = jg >> 11, j = jg & 2047;
        __nv_bfloat16 h, l; split2(t[tx][ty + 8 * r], h, l);
        const long base = ((long)n * 128 + b * 64 + k) * 4096 + j;
        out[base] = h; out[base + 2048] = l;
    }
}

// w_fc -> B2t[n][d][j]=hi(w_fc[j*16+n][d]), [..][2048+j]=lo  grid(32,64,16)
__global__ void conv_wfc(const float* __restrict__ wfc, __nv_bfloat16* __restrict__ out)
{
    __shared__ float t[32][33];
    const int n = blockIdx.z, j0 = blockIdx.y * 32, d0 = blockIdx.x * 32;
    const int tx = threadIdx.x, ty = threadIdx.y;
    #pragma unroll
    for (int r = 0; r < 4; r++)
        t[ty + 8 * r][tx] = wfc[(long)((j0 + ty + 8 * r) * 16 + n) * 1024 + d0 + tx];
    __syncthreads();
    #pragma unroll
    for (int r = 0; r < 4; r++) {
        __nv_bfloat16 h, l; split2(t[tx][ty + 8 * r], h, l);
        const long base = ((long)n * 1024 + d0 + ty + 8 * r) * 4096 + j0 + tx;
        out[base] = h; out[base + 2048] = l;
    }
}

// Ttmp[16][128][1024] -> B3t[b][d][kk]=hi(T[b][kk][d]), [..][1024+kk]=lo  grid(32,32,2)
__global__ void conv_t(const float* __restrict__ Tt, __nv_bfloat16* __restrict__ out)
{
    __shared__ float t[32][33];
    const int b = blockIdx.z, d0 = blockIdx.y * 32, kk0 = blockIdx.x * 32;
    const int tx = threadIdx.x, ty = threadIdx.y;
    #pragma unroll
    for (int r = 0; r < 4; r++) {
        const int kk = kk0 + ty + 8 * r, n = kk >> 6, k = kk & 63;
        t[ty + 8 * r][tx] = Tt[((long)n * 128 + b * 64 + k) * 1024 + d0 + tx];
    }
    __syncthreads();
    #pragma unroll
    for (int r = 0; r < 4; r++) {
        __nv_bfloat16 h, l; split2(t[tx][ty + 8 * r], h, l);
        const long base = ((long)b * 1024 + d0 + ty + 8 * r) * 2048 + kk0 + tx;
        out[base] = h; out[base + 1024] = l;
    }
}

// ---------------------------------------------------------------------------
// Residual + LayerNorm
// ---------------------------------------------------------------------------
__device__ __forceinline__ float warp_sum(float v) {
    #pragma unroll
    for (int o = 16; o > 0; o >>= 1) v += __shfl_down_sync(0xFFFFFFFFu, v, o);
    return v;
}

__global__ __launch_bounds__(256)
void ln_kernel(const float* __restrict__ x, const float* __restrict__ mid,
               const float* __restrict__ gamma, const float* __restrict__ beta,
               float* __restrict__ y)
{
    __shared__ float red[2][8];
    const long row = blockIdx.x;
    const int  c = threadIdx.x * 4, wid = threadIdx.x >> 5, lan = threadIdx.x & 31;

    const float4 xv = *(const float4*)(x   + row * DM_ + c);
    const float4 ov = *(const float4*)(mid + row * DM_ + c);
    const float v0 = xv.x + ov.x, v1 = xv.y + ov.y, v2 = xv.z + ov.z, v3 = xv.w + ov.w;

    float s  = warp_sum(v0 + v1 + v2 + v3);
    float ss = warp_sum(v0 * v0 + v1 * v1 + v2 * v2 + v3 * v3);
    if (lan == 0) { red[0][wid] = s; red[1][wid] = ss; }
    __syncthreads();
    if (wid == 0) {
        float a = (lan < 8) ? red[0][lan] : 0.0f;
        float b = (lan < 8) ? red[1][lan] : 0.0f;
        a = warp_sum(a); b = warp_sum(b);
        if (lan == 0) { red[0][0] = a * (1.0f / DM_); red[1][0] = b * (1.0f / DM_); }
    }
    __syncthreads();

    const float mean = red[0][0];
    const float rstd = rsqrtf(red[1][0] - mean * mean + 1e-5f);
    const float4 gv = *(const float4*)(gamma + c);
    const float4 bv = *(const float4*)(beta + c);
    float4 o;
    o.x = gv.x * (v0 - mean) * rstd + bv.x;
    o.y = gv.y * (v1 - mean) * rstd + bv.y;
    o.z = gv.z * (v2 - mean) * rstd + bv.z;
    o.w = gv.w * (v3 - mean) * rstd + bv.w;
    *(float4*)(y + row * DM_ + c) = o;
}

// ---------------------------------------------------------------------------
extern "C" void kernel_launch(void* const* d_in, const int* in_sizes, int n_in,
                              void* d_out, int out_size)
{
    const float* x     = (const float*)d_in[0];
    const float* w_qkv = (const float*)d_in[1];
    const float* b_qkv = (const float*)d_in[2];
    const float* w_fc  = (const float*)d_in[3];
    const float* b_fc  = (const float*)d_in[4];
    const float* gamma = (const float*)d_in[5];
    const float* beta  = (const float*)d_in[6];
    float* out = (float*)d_out;

    __nv_bfloat16 *A1, *B1t, *A3, *A2, *B2t, *B3t;
    float *qk, *Tt, *mid, *zb;
    cudaGetSymbolAddress((void**)&A1,  g_A1);
    cudaGetSymbolAddress((void**)&B1t, g_B1t);
    cudaGetSymbolAddress((void**)&qk,  g_qk);
    cudaGetSymbolAddress((void**)&A3,  g_A3);
    cudaGetSymbolAddress((void**)&A2,  g_A2);
    cudaGetSymbolAddress((void**)&B2t, g_B2t);
    cudaGetSymbolAddress((void**)&Tt,  g_Tt);
    cudaGetSymbolAddress((void**)&B3t, g_B3t);
    cudaGetSymbolAddress((void**)&mid, g_mid);
    cudaGetSymbolAddress((void**)&zb,  g_zb);

    cudaFuncSetAttribute(mm_gemm, cudaFuncAttributeMaxDynamicSharedMemorySize, GSMEM_);

    const dim3 tb(32, 8);

    // 1) splits of x and w_qkv
    conv_rows<<<ROWS_ * 1024 / (256 * 4), 256>>>(x, DM_, A1, 1024);
    conv_wqkv<<<dim3(64, 32), tb>>>(w_qkv, B1t);

    // 2) qk = x @ w_qkv[:, :2048] + b_qkv[:2048]     (V is dead code)
    mm_gemm<<<dim3(2048 / 128, ROWS_ / 128, 1), 256, GSMEM_>>>(
        A1, 2048, 0, B1t, 2048, 0, qk, 2048, 0, b_qkv, 1024, 1.0f);

    // 3) splits of Q (rows) and K^T (per-head transpose)
    conv_rows<<<ROWS_ * 1024 / (256 * 4), 256>>>(qk, 2048, A3, 1024);
    conv_a2<<<dim3(2, 128, NH_), tb>>>(qk, A2);

    // 4) w_fc transpose + split (the big one: 134 MB -> 134 MB)
    conv_wfc<<<dim3(32, 64, NH_), tb>>>(w_fc, B2t);

    // 5) Ttmp[n] = (1/8) * K_n^T @ W_n      M=128, N=1024, K=2048, 16 heads
    mm_gemm<<<dim3(1024 / 128, 1, NH_), 256, GSMEM_>>>(
        A2, 4096, 128L * 4096, B2t, 4096, 1024L * 4096,
        Tt, 1024, 128L * 1024, zb, 2048, 0.125f);

    // 6) T transpose + split
    conv_t<<<dim3(32, 32, B_), tb>>>(Tt, B3t);

    // 7) mid[b] = Q[b] @ T[b] + b_fc        M=2048, N=1024, K=1024, batch 2
    mm_gemm<<<dim3(1024 / 128, S_ / 128, B_), 256, GSMEM_>>>(
        A3, 2048, 2048L * 2048, B3t, 2048, 1024L * 2048,
        mid, 1024, (long)S_ * 1024, b_fc, 1024, 1.0f);

    // 8) y = LN(x + mid)
    ln_kernel<<<ROWS_, 256>>>(x, mid, gamma, beta, out);
}

// round 5
// speedup vs baseline: 2.4757x; 1.0768x over previous
#include <cuda_runtime.h>
#include <cuda_bf16.h>
#include <cstdint>

// ---------------------------------------------------------------------------
// Problem constants
// ---------------------------------------------------------------------------
#define B_       2
#define S_       2048
#define DM_      1024
#define NH_      16
#define ROWS_    (B_ * S_)          // 4096

// ---------------------------------------------------------------------------
// Scratch (__device__ globals; no allocation at launch). 1024B-aligned.
// bf16 "split" buffers store [hi | lo] along the contraction dim (2K wide).
// ---------------------------------------------------------------------------
__device__ __align__(1024) __nv_bfloat16 g_A1 [(size_t)ROWS_ * 2048];     // x split
__device__ __align__(1024) __nv_bfloat16 g_B1t[(size_t)2048 * 2048];      // w_qkv[:,:2048]^T split
__device__ __align__(1024) float         g_qk [(size_t)ROWS_ * 2048];     // q|k fp32
__device__ __align__(1024) __nv_bfloat16 g_A3 [(size_t)ROWS_ * 2048];     // Q split
__device__ __align__(1024) __nv_bfloat16 g_A2 [(size_t)NH_ * 128 * 4096]; // K^T split
__device__ __align__(1024) __nv_bfloat16 g_B2t[(size_t)NH_ * DM_ * 4096]; // w_fc^T split
__device__ __align__(1024) float         g_Tt [(size_t)NH_ * 128 * DM_];  // T tmp fp32
__device__ __align__(1024) __nv_bfloat16 g_B3t[(size_t)B_ * DM_ * 2048];  // T^T split
__device__ __align__(1024) float         g_mid[(size_t)ROWS_ * DM_];      // pre-LN out
__device__ __align__(1024) float         g_zb [2048];                     // zero bias

// ---------------------------------------------------------------------------
// PTX helpers (baseline sm_100 ISA only: cp.async, ldmatrix, mma.sync)
// ---------------------------------------------------------------------------
__device__ __forceinline__ uint32_t smem_u32(const void* p) {
    uint32_t a;
    asm("{ .reg .u64 t; cvta.to.shared.u64 t, %1; cvt.u32.u64 %0, t; }" : "=r"(a) : "l"(p));
    return a;
}

#define SW128(off) ((off) ^ (((off) >> 3) & 0x70))

#define CP_ASYNC16(dst, src) \
    asm volatile("cp.async.cg.shared.global [%0], [%1], 16;" :: "r"(dst), "l"(src))
#define CP_COMMIT() asm volatile("cp.async.commit_group;" ::: "memory")

__device__ __forceinline__ void ldsm4(uint32_t* r, uint32_t addr) {
    asm volatile("ldmatrix.sync.aligned.m8n8.x4.shared.b16 {%0,%1,%2,%3}, [%4];"
                 : "=r"(r[0]), "=r"(r[1]), "=r"(r[2]), "=r"(r[3]) : "r"(addr));
}

__device__ __forceinline__ void mma16816(float* d, const uint32_t* a, const uint32_t* b) {
    asm volatile("mma.sync.aligned.m16n8k16.row.col.f32.bf16.bf16.f32 "
                 "{%0,%1,%2,%3}, {%4,%5,%6,%7}, {%8,%9}, {%0,%1,%2,%3};"
                 : "+f"(d[0]), "+f"(d[1]), "+f"(d[2]), "+f"(d[3])
                 : "r"(a[0]), "r"(a[1]), "r"(a[2]), "r"(a[3]), "r"(b[0]), "r"(b[1]));
}

// ---------------------------------------------------------------------------
// Tensor-core GEMM (mma.sync), unified split chunks:
//   C[M,N] = alpha * A[M,K] @ Bt[N,K]^T + bias     (exact 2-term bf16 split)
// Physical operand rows are 2K bf16 ([hi | lo]).  Per 64-wide k-chunk we load
// A-hi, A-lo, B-hi, B-lo once and accumulate hi*hi + lo*hi + hi*lo (lo*lo
// dropped, ~2^-18 relative).  Tile 128x128, 8 warps (2x4), 3-stage cp.async.
// ---------------------------------------------------------------------------
#define BK_     64
#define STAGES_ 3
#define TILE16K (128 * BK_ * 2)            // 16 KB per sub-tile
#define STAGE_  (4 * TILE16K)              // Ahi|Alo|Bhi|Blo = 64 KB
#define GSMEM_  (STAGES_ * STAGE_ + 1024)  // + alignment slack

__global__ __launch_bounds__(256, 1)
void mm_gemm(const __nv_bfloat16* __restrict__ A, long lda, long sA,
             const __nv_bfloat16* __restrict__ Bt, long ldb, long sB,
             float* __restrict__ C, long ldc, long sC,
             const float* __restrict__ bias, int K, float alpha)
{
    extern __shared__ char smem[];
    const uint32_t tbase = (smem_u32(smem) + 1023) & ~1023u;
    const int tid = threadIdx.x, wid = tid >> 5, lane = tid & 31;
    const int wm = wid >> 2, wn = wid & 3;       // warp grid 2 (m) x 4 (n)

    A    += (long)blockIdx.z * sA + (long)blockIdx.y * 128 * lda;
    Bt   += (long)blockIdx.z * sB + (long)blockIdx.x * 128 * ldb;
    C    += (long)blockIdx.z * sC + (long)blockIdx.y * 128 * ldc + (long)blockIdx.x * 128;
    bias += blockIdx.x * 128;

    const int NC = K / BK_;          // k-chunks

    auto load_stage = [&](int c, int s) {
        const uint32_t sb = tbase + s * STAGE_;
        #pragma unroll
        for (int r = 0; r < 4; r++) {
            const int e = tid + r * 256;
            const int row = e >> 3;
            const int c16 = (e & 7) * 16;            // byte col in tile
            const long gcol = (long)c * BK_ + (e & 7) * 8;  // element col (hi)
            const uint32_t so = SW128(row * 128 + c16);
            const __nv_bfloat16* ar = A + (long)row * lda + gcol;
            const __nv_bfloat16* br = Bt + (long)row * ldb + gcol;
            CP_ASYNC16(sb + so,               ar);        // A hi
            CP_ASYNC16(sb + TILE16K + so,     ar + K);    // A lo
            CP_ASYNC16(sb + 2 * TILE16K + so, br);        // B hi
            CP_ASYNC16(sb + 3 * TILE16K + so, br + K);    // B lo
        }
    };

    // ldmatrix per-lane address pieces (j = lane>>3, r = lane&7)
    const int lj = lane >> 3, lr = lane & 7;
    // A x4 tile order: (m0-7,k0-7),(m8-15,k0-7),(m0-7,k8-15),(m8-15,k8-15)
    const int arow_base = wm * 64 + (lj & 1) * 8 + lr;    // + mt*16
    const int acol_base = (lj >> 1) * 16;                 // + ks*32 (bytes)
    // B x4 (n-pair p): (n0-7,k0-7),(n0-7,k8-15),(n8-15,k0-7),(n8-15,k8-15)
    const int brow_base = wn * 32 + (lj >> 1) * 8 + lr;   // + p*16
    const int bcol_base = (lj & 1) * 16;                  // + ks*32 (bytes)

    float acc[4][4][4] = {};   // [mt][nt][reg]

    // Prologue
    for (int c = 0; c < STAGES_ - 1; c++) { load_stage(c, c); CP_COMMIT(); }

    for (int i = 0; i < NC; i++) {
        const int pf = i + STAGES_ - 1;
        if (pf < NC) load_stage(pf, pf % STAGES_);
        CP_COMMIT();
        asm volatile("cp.async.wait_group %0;" :: "n"(STAGES_ - 1));
        __syncthreads();

        const uint32_t sb  = tbase + (i % STAGES_) * STAGE_;
        const uint32_t ahi = sb,               alo = sb + TILE16K;
        const uint32_t bhi = sb + 2 * TILE16K, blo = sb + 3 * TILE16K;

        #pragma unroll
        for (int ks = 0; ks < BK_ / 16; ks++) {
            uint32_t ah[4][4], al[4][4], bh[2][4], bl[2][4];
            #pragma unroll
            for (int mt = 0; mt < 4; mt++) {
                const int row = arow_base + mt * 16;
                const int off = row * 128 + ((acol_base + ks * 32) ^ ((row & 7) << 4));
                ldsm4(ah[mt], ahi + off);
                ldsm4(al[mt], alo + off);
            }
            #pragma unroll
            for (int p = 0; p < 2; p++) {
                const int row = brow_base + p * 16;
                const int off = row * 128 + ((bcol_base + ks * 32) ^ ((row & 7) << 4));
                ldsm4(bh[p], bhi + off);
                ldsm4(bl[p], blo + off);
            }
            #pragma unroll
            for (int mt = 0; mt < 4; mt++)
                #pragma unroll
                for (int nt = 0; nt < 4; nt++) {
                    const uint32_t* bhp = &bh[nt >> 1][(nt & 1) * 2];
                    const uint32_t* blp = &bl[nt >> 1][(nt & 1) * 2];
                    mma16816(acc[mt][nt], ah[mt], bhp);   // hi*hi
                    mma16816(acc[mt][nt], al[mt], bhp);   // lo*hi
                    mma16816(acc[mt][nt], ah[mt], blp);   // hi*lo
                }
        }
        __syncthreads();
    }

    // Epilogue: direct global stores (fp32), bias + alpha
    const int erow = wm * 64 + (lane >> 2);
    const int ecol = wn * 32 + (lane & 3) * 2;
    #pragma unroll
    for (int mt = 0; mt < 4; mt++) {
        #pragma unroll
        for (int nt = 0; nt < 4; nt++) {
            const int col = ecol + nt * 8;
            const float b0 = bias[col], b1 = bias[col + 1];
            float2 v;
            v.x = alpha * acc[mt][nt][0] + b0;
            v.y = alpha * acc[mt][nt][1] + b1;
            *(float2*)(C + (long)(erow + mt * 16) * ldc + col) = v;
            v.x = alpha * acc[mt][nt][2] + b0;
            v.y = alpha * acc[mt][nt][3] + b1;
            *(float2*)(C + (long)(erow + mt * 16 + 8) * ldc + col) = v;
        }
    }
}

// ---------------------------------------------------------------------------
// Split conversions
// ---------------------------------------------------------------------------
__device__ __forceinline__ void split2(float a, __nv_bfloat16& h, __nv_bfloat16& l) {
    h = __float2bfloat16(a);
    l = __float2bfloat16(a - __bfloat162float(h));
}

// Row-major split: out[r][c]=hi(in[r][c]), out[r][Csel+c]=lo ; out row = 2*Csel
__global__ __launch_bounds__(256)
void conv_rows(const float* __restrict__ in, long ldin,
               __nv_bfloat16* __restrict__ out, int Csel)
{
    const long idx = (long)blockIdx.x * 256 + threadIdx.x;
    const long r = idx / (Csel / 4);
    const int  c = (int)(idx % (Csel / 4)) * 4;
    const float4 v = *(const float4*)(in + r * ldin + c);
    __nv_bfloat16 h0, h1, h2, h3, l0, l1, l2, l3;
    split2(v.x, h0, l0); split2(v.y, h1, l1);
    split2(v.z, h2, l2); split2(v.w, h3, l3);
    __nv_bfloat16* po = out + r * 2 * Csel + c;
    *(__nv_bfloat162*)(po)            = __halves2bfloat162(h0, h1);
    *(__nv_bfloat162*)(po + 2)        = __halves2bfloat162(h2, h3);
    *(__nv_bfloat162*)(po + Csel)     = __halves2bfloat162(l0, l1);
    *(__nv_bfloat162*)(po + Csel + 2) = __halves2bfloat162(l2, l3);
}

// w_qkv[:, :2048] -> B1t[n][c]=hi(w[c][n]), [n][1024+c]=lo   (ld w = 3072)
__global__ void conv_wqkv(const float* __restrict__ w, __nv_bfloat16* __restrict__ out)
{
    __shared__ float t[32][33];
    const int c0 = blockIdx.y * 32, n0 = blockIdx.x * 32;
    const int tx = threadIdx.x, ty = threadIdx.y;
    #pragma unroll
    for (int r = 0; r < 4; r++)
        t[ty + 8 * r][tx] = w[(long)(c0 + ty + 8 * r) * 3072 + n0 + tx];
    __syncthreads();
    #pragma unroll
    for (int r = 0; r < 4; r++) {
        __nv_bfloat16 h, l; split2(t[tx][ty + 8 * r], h, l);
        const long base = (long)(n0 + ty + 8 * r) * 2048 + c0 + tx;
        out[base] = h; out[base + 1024] = l;
    }
}

// qk K-half -> A2[n][b*64+k][j]=hi, [..][2048+j]=lo   grid(2,128,16)
__global__ void conv_a2(const float* __restrict__ qk, __nv_bfloat16* __restrict__ out)
{
    __shared__ float t[32][33];
    const int n = blockIdx.z, jg0 = blockIdx.y * 32, k0 = blockIdx.x * 32;
    const int tx = threadIdx.x, ty = threadIdx.y;
    #pragma unroll
    for (int r = 0; r < 4; r++)
        t[ty + 8 * r][tx] = qk[(long)(jg0 + ty + 8 * r) * 2048 + 1024 + n * 64 + k0 + tx];
    __syncthreads();
    #pragma unroll
    for (int r = 0; r < 4; r++) {
        const int k = k0 + ty + 8 * r;
        const int jg = jg0 + tx, b = jg >> 11, j = jg & 2047;
        __nv_bfloat16 h, l; split2(t[tx][ty + 8 * r], h, l);
        const long base = ((long)n * 128 + b * 64 + k) * 4096 + j;
        out[base] = h; out[base + 2048] = l;
    }
}

// w_fc -> B2t[n][d][j]=hi(w_fc[j*16+n][d]), [..][2048+j]=lo  grid(32,64,16)
__global__ void conv_wfc(const float* __restrict__ wfc, __nv_bfloat16* __restrict__ out)
{
    __shared__ float t[32][33];
    const int n = blockIdx.z, j0 = blockIdx.y * 32, d0 = blockIdx.x * 32;
    const int tx = threadIdx.x, ty = threadIdx.y;
    #pragma unroll
    for (int r = 0; r < 4; r++)
        t[ty + 8 * r][tx] = wfc[(long)((j0 + ty + 8 * r) * 16 + n) * 1024 + d0 + tx];
    __syncthreads();
    #pragma unroll
    for (int r = 0; r < 4; r++) {
        __nv_bfloat16 h, l; split2(t[tx][ty + 8 * r], h, l);
        const long base = ((long)n * 1024 + d0 + ty + 8 * r) * 4096 + j0 + tx;
        out[base] = h; out[base + 2048] = l;
    }
}

// Ttmp[16][128][1024] -> B3t[b][d][kk]=hi(T[b][kk][d]), [..][1024+kk]=lo  grid(32,32,2)
__global__ void conv_t(const float* __restrict__ Tt, __nv_bfloat16* __restrict__ out)
{
    __shared__ float t[32][33];
    const int b = blockIdx.z, d0 = blockIdx.y * 32, kk0 = blockIdx.x * 32;
    const int tx = threadIdx.x, ty = threadIdx.y;
    #pragma unroll
    for (int r = 0; r < 4; r++) {
        const int kk = kk0 + ty + 8 * r, n = kk >> 6, k = kk & 63;
        t[ty + 8 * r][tx] = Tt[((long)n * 128 + b * 64 + k) * 1024 + d0 + tx];
    }
    __syncthreads();
    #pragma unroll
    for (int r = 0; r < 4; r++) {
        __nv_bfloat16 h, l; split2(t[tx][ty + 8 * r], h, l);
        const long base = ((long)b * 1024 + d0 + ty + 8 * r) * 2048 + kk0 + tx;
        out[base] = h; out[base + 1024] = l;
    }
}

// ---------------------------------------------------------------------------
// Residual + LayerNorm
// ---------------------------------------------------------------------------
__device__ __forceinline__ float warp_sum(float v) {
    #pragma unroll
    for (int o = 16; o > 0; o >>= 1) v += __shfl_down_sync(0xFFFFFFFFu, v, o);
    return v;
}

__global__ __launch_bounds__(256)
void ln_kernel(const float* __restrict__ x, const float* __restrict__ mid,
               const float* __restrict__ gamma, const float* __restrict__ beta,
               float* __restrict__ y)
{
    __shared__ float red[2][8];
    const long row = blockIdx.x;
    const int  c = threadIdx.x * 4, wid = threadIdx.x >> 5, lan = threadIdx.x & 31;

    const float4 xv = *(const float4*)(x   + row * DM_ + c);
    const float4 ov = *(const float4*)(mid + row * DM_ + c);
    const float v0 = xv.x + ov.x, v1 = xv.y + ov.y, v2 = xv.z + ov.z, v3 = xv.w + ov.w;

    float s  = warp_sum(v0 + v1 + v2 + v3);
    float ss = warp_sum(v0 * v0 + v1 * v1 + v2 * v2 + v3 * v3);
    if (lan == 0) { red[0][wid] = s; red[1][wid] = ss; }
    __syncthreads();
    if (wid == 0) {
        float a = (lan < 8) ? red[0][lan] : 0.0f;
        float b = (lan < 8) ? red[1][lan] : 0.0f;
        a = warp_sum(a); b = warp_sum(b);
        if (lan == 0) { red[0][0] = a * (1.0f / DM_); red[1][0] = b * (1.0f / DM_); }
    }
    __syncthreads();

    const float mean = red[0][0];
    const float rstd = rsqrtf(red[1][0] - mean * mean + 1e-5f);
    const float4 gv = *(const float4*)(gamma + c);
    const float4 bv = *(const float4*)(beta + c);
    float4 o;
    o.x = gv.x * (v0 - mean) * rstd + bv.x;
    o.y = gv.y * (v1 - mean) * rstd + bv.y;
    o.z = gv.z * (v2 - mean) * rstd + bv.z;
    o.w = gv.w * (v3 - mean) * rstd + bv.w;
    *(float4*)(y + row * DM_ + c) = o;
}

// ---------------------------------------------------------------------------
extern "C" void kernel_launch(void* const* d_in, const int* in_sizes, int n_in,
                              void* d_out, int out_size)
{
    const float* x     = (const float*)d_in[0];
    const float* w_qkv = (const float*)d_in[1];
    const float* b_qkv = (const float*)d_in[2];
    const float* w_fc  = (const float*)d_in[3];
    const float* b_fc  = (const float*)d_in[4];
    const float* gamma = (const float*)d_in[5];
    const float* beta  = (const float*)d_in[6];
    float* out = (float*)d_out;

    __nv_bfloat16 *A1, *B1t, *A3, *A2, *B2t, *B3t;
    float *qk, *Tt, *mid, *zb;
    cudaGetSymbolAddress((void**)&A1,  g_A1);
    cudaGetSymbolAddress((void**)&B1t, g_B1t);
    cudaGetSymbolAddress((void**)&qk,  g_qk);
    cudaGetSymbolAddress((void**)&A3,  g_A3);
    cudaGetSymbolAddress((void**)&A2,  g_A2);
    cudaGetSymbolAddress((void**)&B2t, g_B2t);
    cudaGetSymbolAddress((void**)&Tt,  g_Tt);
    cudaGetSymbolAddress((void**)&B3t, g_B3t);
    cudaGetSymbolAddress((void**)&mid, g_mid);
    cudaGetSymbolAddress((void**)&zb,  g_zb);

    cudaFuncSetAttribute(mm_gemm, cudaFuncAttributeMaxDynamicSharedMemorySize, GSMEM_);

    const dim3 tb(32, 8);

    // 1) splits of x and w_qkv
    conv_rows<<<ROWS_ * 1024 / (256 * 4), 256>>>(x, DM_, A1, 1024);
    conv_wqkv<<<dim3(64, 32), tb>>>(w_qkv, B1t);

    // 2) qk = x @ w_qkv[:, :2048] + b_qkv[:2048]     (V is dead code)
    mm_gemm<<<dim3(2048 / 128, ROWS_ / 128, 1), 256, GSMEM_>>>(
        A1, 2048, 0, B1t, 2048, 0, qk, 2048, 0, b_qkv, 1024, 1.0f);

    // 3) splits of Q (rows) and K^T (per-head transpose)
    conv_rows<<<ROWS_ * 1024 / (256 * 4), 256>>>(qk, 2048, A3, 1024);
    conv_a2<<<dim3(2, 128, NH_), tb>>>(qk, A2);

    // 4) w_fc transpose + split (the big one: 134 MB -> 134 MB)
    conv_wfc<<<dim3(32, 64, NH_), tb>>>(w_fc, B2t);

    // 5) Ttmp[n] = (1/8) * K_n^T @ W_n      M=128, N=1024, K=2048, 16 heads
    mm_gemm<<<dim3(1024 / 128, 1, NH_), 256, GSMEM_>>>(
        A2, 4096, 128L * 4096, B2t, 4096, 1024L * 4096,
        Tt, 1024, 128L * 1024, zb, 2048, 0.125f);

    // 6) T transpose + split
    conv_t<<<dim3(32, 32, B_), tb>>>(Tt, B3t);

    // 7) mid[b] = Q[b] @ T[b] + b_fc        M=2048, N=1024, K=1024, batch 2
    mm_gemm<<<dim3(1024 / 128, S_ / 128, B_), 256, GSMEM_>>>(
        A3, 2048, 2048L * 2048, B3t, 2048, 1024L * 2048,
        mid, 1024, (long)S_ * 1024, b_fc, 1024, 1.0f);

    // 8) y = LN(x + mid)
    ln_kernel<<<ROWS_, 256>>>(x, mid, gamma, beta, out);
}

// round 6
// speedup vs baseline: 3.2599x; 1.3168x over previous
#include <cuda_runtime.h>
#include <cuda_fp16.h>
#include <cstdint>

// ---------------------------------------------------------------------------
// Problem constants
// ---------------------------------------------------------------------------
#define B_       2
#define S_       2048
#define DM_      1024
#define NH_      16
#define ROWS_    (B_ * S_)          // 4096

// ---------------------------------------------------------------------------
// Scratch (__device__ globals; no allocation at launch). 1024B-aligned.
// A-side fp16 "split" buffers: [hi | lo] along contraction dim (2K wide).
// B-side fp16 single-rounded buffers: K wide.
// ---------------------------------------------------------------------------
__device__ __align__(1024) __half g_A1 [(size_t)ROWS_ * 2048];      // x split       [4096][2048]
__device__ __align__(1024) __half g_B1t[(size_t)2048 * 1024];       // w_qkv^T f16   [2048][1024]
__device__ __align__(1024) float  g_qk [(size_t)ROWS_ * 2048];      // q|k fp32
__device__ __align__(1024) __half g_A3 [(size_t)ROWS_ * 2048];      // Q split       [4096][2048]
__device__ __align__(1024) __half g_A2 [(size_t)NH_ * 128 * 4096];  // K^T split     [16][128][4096]
__device__ __align__(1024) __half g_B2t[(size_t)NH_ * DM_ * 2048];  // w_fc^T f16    [16][1024][2048]
__device__ __align__(1024) float  g_Tt [(size_t)NH_ * 128 * DM_];   // T tmp fp32    [16][128][1024]
__device__ __align__(1024) __half g_B3t[(size_t)B_ * DM_ * 1024];   // T^T f16       [2][1024][1024]
__device__ __align__(1024) float  g_mid[(size_t)ROWS_ * DM_];       // pre-LN out
__device__ __align__(1024) float  g_zb [2048];                      // zero bias

// ---------------------------------------------------------------------------
// PTX helpers (baseline sm_100 ISA: cp.async, ldmatrix, mma.sync)
// ---------------------------------------------------------------------------
__device__ __forceinline__ uint32_t smem_u32(const void* p) {
    uint32_t a;
    asm("{ .reg .u64 t; cvta.to.shared.u64 t, %1; cvt.u32.u64 %0, t; }" : "=r"(a) : "l"(p));
    return a;
}

#define SW128(off) ((off) ^ (((off) >> 3) & 0x70))

#define CP_ASYNC16(dst, src) \
    asm volatile("cp.async.cg.shared.global [%0], [%1], 16;" :: "r"(dst), "l"(src))
#define CP_COMMIT() asm volatile("cp.async.commit_group;" ::: "memory")

__device__ __forceinline__ void ldsm4(uint32_t* r, uint32_t addr) {
    asm volatile("ldmatrix.sync.aligned.m8n8.x4.shared.b16 {%0,%1,%2,%3}, [%4];"
                 : "=r"(r[0]), "=r"(r[1]), "=r"(r[2]), "=r"(r[3]) : "r"(addr));
}

__device__ __forceinline__ void mma16816(float* d, const uint32_t* a, const uint32_t* b) {
    asm volatile("mma.sync.aligned.m16n8k16.row.col.f32.f16.f16.f32 "
                 "{%0,%1,%2,%3}, {%4,%5,%6,%7}, {%8,%9}, {%0,%1,%2,%3};"
                 : "+f"(d[0]), "+f"(d[1]), "+f"(d[2]), "+f"(d[3])
                 : "r"(a[0]), "r"(a[1]), "r"(a[2]), "r"(a[3]), "r"(b[0]), "r"(b[1]));
}

// ---------------------------------------------------------------------------
// Tensor-core GEMM (mma.sync), asymmetric fp16 split:
//   C[M,N] = alpha * A[M,K] @ Bt[N,K]^T + bias
// A rows are 2K fp16 ([hi | lo], a = hi + lo exactly to 2^-22); Bt rows are
// K fp16 (single rounding). acc += ahi*b + alo*b  (2 MMAs per tile).
// Tile 128x128, 8 warps (2x4), 3-stage cp.async pipeline, SW128 smem.
// ---------------------------------------------------------------------------
#define BK_     64
#define STAGES_ 3
#define TILE16K (128 * BK_ * 2)            // 16 KB per sub-tile
#define STAGE_  (3 * TILE16K)              // Ahi|Alo|B = 48 KB
#define GSMEM_  (STAGES_ * STAGE_ + 1024)  // + alignment slack

__global__ __launch_bounds__(256, 1)
void mm_gemm(const __half* __restrict__ A, long lda, long sA,
             const __half* __restrict__ Bt, long ldb, long sB,
             float* __restrict__ C, long ldc, long sC,
             const float* __restrict__ bias, int K, float alpha)
{
    extern __shared__ char smem[];
    const uint32_t tbase = (smem_u32(smem) + 1023) & ~1023u;
    const int tid = threadIdx.x, wid = tid >> 5, lane = tid & 31;
    const int wm = wid >> 2, wn = wid & 3;       // warp grid 2 (m) x 4 (n)

    A    += (long)blockIdx.z * sA + (long)blockIdx.y * 128 * lda;
    Bt   += (long)blockIdx.z * sB + (long)blockIdx.x * 128 * ldb;
    C    += (long)blockIdx.z * sC + (long)blockIdx.y * 128 * ldc + (long)blockIdx.x * 128;
    bias += blockIdx.x * 128;

    const int NC = K / BK_;          // k-chunks

    auto load_stage = [&](int c, int s) {
        const uint32_t sb = tbase + s * STAGE_;
        #pragma unroll
        for (int r = 0; r < 4; r++) {
            const int e = tid + r * 256;
            const int row = e >> 3;
            const int c16 = (e & 7) * 16;                  // byte col in tile
            const long gcol = (long)c * BK_ + (e & 7) * 8; // element col
            const uint32_t so = SW128(row * 128 + c16);
            const __half* ar = A + (long)row * lda + gcol;
            CP_ASYNC16(sb + so,               ar);                               // A hi
            CP_ASYNC16(sb + TILE16K + so,     ar + K);                           // A lo
            CP_ASYNC16(sb + 2 * TILE16K + so, Bt + (long)row * ldb + gcol);      // B
        }
    };

    // ldmatrix per-lane address pieces (j = lane>>3, r = lane&7)
    const int lj = lane >> 3, lr = lane & 7;
    // A x4 tile order: (m0-7,k0-7),(m8-15,k0-7),(m0-7,k8-15),(m8-15,k8-15)
    const int arow_base = wm * 64 + (lj & 1) * 8 + lr;    // + mt*16
    const int acol_base = (lj >> 1) * 16;                 // + ks*32 (bytes)
    // B x4 (n-pair p): (n0-7,k0-7),(n0-7,k8-15),(n8-15,k0-7),(n8-15,k8-15)
    const int brow_base = wn * 32 + (lj >> 1) * 8 + lr;   // + p*16
    const int bcol_base = (lj & 1) * 16;                  // + ks*32 (bytes)

    float acc[4][4][4] = {};   // [mt][nt][reg]

    // Prologue
    for (int c = 0; c < STAGES_ - 1; c++) { load_stage(c, c); CP_COMMIT(); }

    for (int i = 0; i < NC; i++) {
        const int pf = i + STAGES_ - 1;
        if (pf < NC) load_stage(pf, pf % STAGES_);
        CP_COMMIT();
        asm volatile("cp.async.wait_group %0;" :: "n"(STAGES_ - 1));
        __syncthreads();

        const uint32_t sb  = tbase + (i % STAGES_) * STAGE_;
        const uint32_t ahi = sb, alo = sb + TILE16K, bsm = sb + 2 * TILE16K;

        #pragma unroll
        for (int ks = 0; ks < BK_ / 16; ks++) {
            uint32_t ah[4][4], al[4][4], bf[2][4];
            #pragma unroll
            for (int mt = 0; mt < 4; mt++) {
                const int row = arow_base + mt * 16;
                const int off = row * 128 + ((acol_base + ks * 32) ^ ((row & 7) << 4));
                ldsm4(ah[mt], ahi + off);
                ldsm4(al[mt], alo + off);
            }
            #pragma unroll
            for (int p = 0; p < 2; p++) {
                const int row = brow_base + p * 16;
                const int off = row * 128 + ((bcol_base + ks * 32) ^ ((row & 7) << 4));
                ldsm4(bf[p], bsm + off);
            }
            #pragma unroll
            for (int mt = 0; mt < 4; mt++)
                #pragma unroll
                for (int nt = 0; nt < 4; nt++) {
                    const uint32_t* bp = &bf[nt >> 1][(nt & 1) * 2];
                    mma16816(acc[mt][nt], ah[mt], bp);   // hi * b
                    mma16816(acc[mt][nt], al[mt], bp);   // lo * b
                }
        }
        __syncthreads();
    }

    // Epilogue: direct global stores (fp32), bias + alpha
    const int erow = wm * 64 + (lane >> 2);
    const int ecol = wn * 32 + (lane & 3) * 2;
    #pragma unroll
    for (int mt = 0; mt < 4; mt++) {
        #pragma unroll
        for (int nt = 0; nt < 4; nt++) {
            const int col = ecol + nt * 8;
            const float b0 = bias[col], b1 = bias[col + 1];
            float2 v;
            v.x = alpha * acc[mt][nt][0] + b0;
            v.y = alpha * acc[mt][nt][1] + b1;
            *(float2*)(C + (long)(erow + mt * 16) * ldc + col) = v;
            v.x = alpha * acc[mt][nt][2] + b0;
            v.y = alpha * acc[mt][nt][3] + b1;
            *(float2*)(C + (long)(erow + mt * 16 + 8) * ldc + col) = v;
        }
    }
}

// ---------------------------------------------------------------------------
// Conversions
// ---------------------------------------------------------------------------
__device__ __forceinline__ void split2h(float a, __half& h, __half& l) {
    h = __float2half_rn(a);
    l = __float2half_rn(a - __half2float(h));
}

// Row-major split: out[r][c]=hi(in[r][c]), out[r][Csel+c]=lo ; out row = 2*Csel
__global__ __launch_bounds__(256)
void conv_rows(const float* __restrict__ in, long ldin,
               __half* __restrict__ out, int Csel)
{
    const long idx = (long)blockIdx.x * 256 + threadIdx.x;
    const long r = idx / (Csel / 4);
    const int  c = (int)(idx % (Csel / 4)) * 4;
    const float4 v = *(const float4*)(in + r * ldin + c);
    __half h0, h1, h2, h3, l0, l1, l2, l3;
    split2h(v.x, h0, l0); split2h(v.y, h1, l1);
    split2h(v.z, h2, l2); split2h(v.w, h3, l3);
    __half* po = out + r * 2 * Csel + c;
    *(__half2*)(po)            = __halves2half2(h0, h1);
    *(__half2*)(po + 2)        = __halves2half2(h2, h3);
    *(__half2*)(po + Csel)     = __halves2half2(l0, l1);
    *(__half2*)(po + Csel + 2) = __halves2half2(l2, l3);
}

// w_qkv[:, :2048] -> B1t[n][c] = f16(w[c][n])   (ld w = 3072), single rounding
__global__ void conv_wqkv(const float* __restrict__ w, __half* __restrict__ out)
{
    __shared__ float t[32][33];
    const int c0 = blockIdx.y * 32, n0 = blockIdx.x * 32;
    const int tx = threadIdx.x, ty = threadIdx.y;
    #pragma unroll
    for (int r = 0; r < 4; r++)
        t[ty + 8 * r][tx] = w[(long)(c0 + ty + 8 * r) * 3072 + n0 + tx];
    __syncthreads();
    #pragma unroll
    for (int r = 0; r < 4; r++)
        out[(long)(n0 + ty + 8 * r) * 1024 + c0 + tx] = __float2half_rn(t[tx][ty + 8 * r]);
}

// qk K-half -> A2[n][b*64+k][j]=hi, [..][2048+j]=lo  (split)  grid(2,128,16)
__global__ void conv_a2(const float* __restrict__ qk, __half* __restrict__ out)
{
    __shared__ float t[32][33];
    const int n = blockIdx.z, jg0 = blockIdx.y * 32, k0 = blockIdx.x * 32;
    const int tx = threadIdx.x, ty = threadIdx.y;
    #pragma unroll
    for (int r = 0; r < 4; r++)
        t[ty + 8 * r][tx] = qk[(long)(jg0 + ty + 8 * r) * 2048 + 1024 + n * 64 + k0 + tx];
    __syncthreads();
    #pragma unroll
    for (int r = 0; r < 4; r++) {
        const int k = k0 + ty + 8 * r;
        const int jg = jg0 + tx, b = jg >> 11, j = jg & 2047;
        __half h, l; split2h(t[tx][ty + 8 * r], h, l);
        const long base = ((long)n * 128 + b * 64 + k) * 4096 + j;
        out[base] = h; out[base + 2048] = l;
    }
}

// w_fc -> B2t[n][d][j] = f16(w_fc[j*16+n][d])  (single)  grid(32,64,16)
__global__ void conv_wfc(const float* __restrict__ wfc, __half* __restrict__ out)
{
    __shared__ float t[32][33];
    const int n = blockIdx.z, j0 = blockIdx.y * 32, d0 = blockIdx.x * 32;
    const int tx = threadIdx.x, ty = threadIdx.y;
    #pragma unroll
    for (int r = 0; r < 4; r++)
        t[ty + 8 * r][tx] = wfc[(long)((j0 + ty + 8 * r) * 16 + n) * 1024 + d0 + tx];
    __syncthreads();
    #pragma unroll
    for (int r = 0; r < 4; r++)
        out[((long)n * 1024 + d0 + ty + 8 * r) * 2048 + j0 + tx] =
            __float2half_rn(t[tx][ty + 8 * r]);
}

// Ttmp[16][128][1024] -> B3t[b][d][kk] = f16(T[b][kk][d])  (single)  grid(32,32,2)
__global__ void conv_t(const float* __restrict__ Tt, __half* __restrict__ out)
{
    __shared__ float t[32][33];
    const int b = blockIdx.z, d0 = blockIdx.y * 32, kk0 = blockIdx.x * 32;
    const int tx = threadIdx.x, ty = threadIdx.y;
    #pragma unroll
    for (int r = 0; r < 4; r++) {
        const int kk = kk0 + ty + 8 * r, n = kk >> 6, k = kk & 63;
        t[ty + 8 * r][tx] = Tt[((long)n * 128 + b * 64 + k) * 1024 + d0 + tx];
    }
    __syncthreads();
    #pragma unroll
    for (int r = 0; r < 4; r++)
        out[((long)b * 1024 + d0 + ty + 8 * r) * 1024 + kk0 + tx] =
            __float2half_rn(t[tx][ty + 8 * r]);
}

// ---------------------------------------------------------------------------
// Residual + LayerNorm
// ---------------------------------------------------------------------------
__device__ __forceinline__ float warp_sum(float v) {
    #pragma unroll
    for (int o = 16; o > 0; o >>= 1) v += __shfl_down_sync(0xFFFFFFFFu, v, o);
    return v;
}

__global__ __launch_bounds__(256)
void ln_kernel(const float* __restrict__ x, const float* __restrict__ mid,
               const float* __restrict__ gamma, const float* __restrict__ beta,
               float* __restrict__ y)
{
    __shared__ float red[2][8];
    const long row = blockIdx.x;
    const int  c = threadIdx.x * 4, wid = threadIdx.x >> 5, lan = threadIdx.x & 31;

    const float4 xv = *(const float4*)(x   + row * DM_ + c);
    const float4 ov = *(const float4*)(mid + row * DM_ + c);
    const float v0 = xv.x + ov.x, v1 = xv.y + ov.y, v2 = xv.z + ov.z, v3 = xv.w + ov.w;

    float s  = warp_sum(v0 + v1 + v2 + v3);
    float ss = warp_sum(v0 * v0 + v1 * v1 + v2 * v2 + v3 * v3);
    if (lan == 0) { red[0][wid] = s; red[1][wid] = ss; }
    __syncthreads();
    if (wid == 0) {
        float a = (lan < 8) ? red[0][lan] : 0.0f;
        float b = (lan < 8) ? red[1][lan] : 0.0f;
        a = warp_sum(a); b = warp_sum(b);
        if (lan == 0) { red[0][0] = a * (1.0f / DM_); red[1][0] = b * (1.0f / DM_); }
    }
    __syncthreads();

    const float mean = red[0][0];
    const float rstd = rsqrtf(red[1][0] - mean * mean + 1e-5f);
    const float4 gv = *(const float4*)(gamma + c);
    const float4 bv = *(const float4*)(beta + c);
    float4 o;
    o.x = gv.x * (v0 - mean) * rstd + bv.x;
    o.y = gv.y * (v1 - mean) * rstd + bv.y;
    o.z = gv.z * (v2 - mean) * rstd + bv.z;
    o.w = gv.w * (v3 - mean) * rstd + bv.w;
    *(float4*)(y + row * DM_ + c) = o;
}

// ---------------------------------------------------------------------------
extern "C" void kernel_launch(void* const* d_in, const int* in_sizes, int n_in,
                              void* d_out, int out_size)
{
    const float* x     = (const float*)d_in[0];
    const float* w_qkv = (const float*)d_in[1];
    const float* b_qkv = (const float*)d_in[2];
    const float* w_fc  = (const float*)d_in[3];
    const float* b_fc  = (const float*)d_in[4];
    const float* gamma = (const float*)d_in[5];
    const float* beta  = (const float*)d_in[6];
    float* out = (float*)d_out;

    __half *A1, *B1t, *A3, *A2, *B2t, *B3t;
    float *qk, *Tt, *mid, *zb;
    cudaGetSymbolAddress((void**)&A1,  g_A1);
    cudaGetSymbolAddress((void**)&B1t, g_B1t);
    cudaGetSymbolAddress((void**)&qk,  g_qk);
    cudaGetSymbolAddress((void**)&A3,  g_A3);
    cudaGetSymbolAddress((void**)&A2,  g_A2);
    cudaGetSymbolAddress((void**)&B2t, g_B2t);
    cudaGetSymbolAddress((void**)&Tt,  g_Tt);
    cudaGetSymbolAddress((void**)&B3t, g_B3t);
    cudaGetSymbolAddress((void**)&mid, g_mid);
    cudaGetSymbolAddress((void**)&zb,  g_zb);

    cudaFuncSetAttribute(mm_gemm, cudaFuncAttributeMaxDynamicSharedMemorySize, GSMEM_);

    const dim3 tb(32, 8);

    // 1) split x; round w_qkv
    conv_rows<<<ROWS_ * 1024 / (256 * 4), 256>>>(x, DM_, A1, 1024);
    conv_wqkv<<<dim3(64, 32), tb>>>(w_qkv, B1t);

    // 2) qk = x @ w_qkv[:, :2048] + b_qkv[:2048]     (V is dead code)
    mm_gemm<<<dim3(2048 / 128, ROWS_ / 128, 1), 256, GSMEM_>>>(
        A1, 2048, 0, B1t, 1024, 0, qk, 2048, 0, b_qkv, 1024, 1.0f);

    // 3) split Q (rows) and K^T (per-head transpose)
    conv_rows<<<ROWS_ * 1024 / (256 * 4), 256>>>(qk, 2048, A3, 1024);
    conv_a2<<<dim3(2, 128, NH_), tb>>>(qk, A2);

    // 4) w_fc transpose + fp16 round (134 MB read -> 67 MB write)
    conv_wfc<<<dim3(32, 64, NH_), tb>>>(w_fc, B2t);

    // 5) Ttmp[n] = (1/8) * K_n^T @ W_n      M=128, N=1024, K=2048, 16 heads
    mm_gemm<<<dim3(1024 / 128, 1, NH_), 256, GSMEM_>>>(
        A2, 4096, 128L * 4096, B2t, 2048, 1024L * 2048,
        Tt, 1024, 128L * 1024, zb, 2048, 0.125f);

    // 6) T transpose + fp16 round
    conv_t<<<dim3(32, 32, B_), tb>>>(Tt, B3t);

    // 7) mid[b] = Q[b] @ T[b] + b_fc        M=2048, N=1024, K=1024, batch 2
    mm_gemm<<<dim3(1024 / 128, S_ / 128, B_), 256, GSMEM_>>>(
        A3, 2048, 2048L * 2048, B3t, 1024, 1024L * 1024,
        mid, 1024, (long)S_ * 1024, b_fc, 1024, 1.0f);

    // 8) y = LN(x + mid)
    ln_kernel<<<ROWS_, 256>>>(x, mid, gamma, beta, out);
}